// round 10
// baseline (speedup 1.0000x reference)
#include <cuda_runtime.h>
#include <cstdint>

#define NF     51
#define UNITS  128
#define G3     384
#define TENC   50
#define NDEC   27
#define GAMMA  28
#define OUTD   102
#define KW     13056          // UNITS*OUTD
#define NW     13158
#define BTOT   8192
#define TSEQ   64
#define GRID   148
#define NTH    896            // 128 cols x 7 row-groups
#define ROWS   56             // max rows per CTA (8 per thread x 7 groups)
#define RP     60             // padded row stride (floats), 16B-aligned
#define KTOT   179            // 128 h + 51 input
#define KPAD   180            // 90 pairs
#define NP     90
#define TSP    58             // ts stride
#define CC     0.5413248546129181f

#define HS_F   (KPAD * RP)            // includes zero pad row k=179
#define TS_F   (OUTD * TSP)
#define SMFLOATS (HS_F + TS_F)

__device__ __align__(16) float g_Wp4[NP * 128 * 4];  // (wz0,wr0,wz1,wr1) per [pair][col]
__device__ __align__(16) float g_Wp2[NP * 128 * 2];  // (wh0,wh1)         per [pair][col]
__device__ __align__(16) float g_wdec[GAMMA * NW];
__device__ __align__(16) float g_eps[NDEC * BTOT * NF];

typedef unsigned long long u64;
typedef unsigned int u32;

// ---------- f32x2 helpers ----------
__device__ __forceinline__ u64 pk2(float lo, float hi) {
    u64 r; asm("mov.b64 %0, {%1, %2};" : "=l"(r) : "f"(lo), "f"(hi)); return r;
}
__device__ __forceinline__ float2 upk2(u64 v) {
    float2 f; asm("mov.b64 {%0, %1}, %2;" : "=f"(f.x), "=f"(f.y) : "l"(v)); return f;
}
__device__ __forceinline__ void fma2(u64& d, u64 a, u64 b) {
    asm("fma.rn.f32x2 %0, %1, %2, %0;" : "+l"(d) : "l"(a), "l"(b));
}

// ---------- JAX threefry2x32 (exact) ----------
__device__ __forceinline__ uint2 tf2x32(u32 k0, u32 k1, u32 x0, u32 x1) {
    u32 k2 = k0 ^ k1 ^ 0x1BD11BDAu;
#define TFR(r) { x0 += x1; x1 = (x1 << (r)) | (x1 >> (32 - (r))); x1 ^= x0; }
    x0 += k0; x1 += k1;
    TFR(13) TFR(15) TFR(26) TFR(6)   x0 += k1; x1 += k2 + 1u;
    TFR(17) TFR(29) TFR(16) TFR(24)  x0 += k2; x1 += k0 + 2u;
    TFR(13) TFR(15) TFR(26) TFR(6)   x0 += k0; x1 += k1 + 3u;
    TFR(17) TFR(29) TFR(16) TFR(24)  x0 += k1; x1 += k2 + 4u;
    TFR(13) TFR(15) TFR(26) TFR(6)   x0 += k2; x1 += k0 + 5u;
#undef TFR
    return make_uint2(x0, x1);
}

// XLA ErfInv f32 (Giles polynomial)
__device__ __forceinline__ float erfinv_f(float x) {
    float w = -log1pf(-x * x);
    float p;
    if (w < 5.0f) {
        w -= 2.5f;
        p = 2.81022636e-08f;
        p = fmaf(p, w, 3.43273939e-07f);
        p = fmaf(p, w, -3.5233877e-06f);
        p = fmaf(p, w, -4.39150654e-06f);
        p = fmaf(p, w, 0.00021858087f);
        p = fmaf(p, w, -0.00125372503f);
        p = fmaf(p, w, -0.00417768164f);
        p = fmaf(p, w, 0.246640727f);
        p = fmaf(p, w, 1.50140941f);
    } else {
        w = sqrtf(w) - 3.0f;
        p = -0.000200214257f;
        p = fmaf(p, w, 0.000100950558f);
        p = fmaf(p, w, 0.00134934322f);
        p = fmaf(p, w, -0.00367342844f);
        p = fmaf(p, w, 0.00573950773f);
        p = fmaf(p, w, -0.0076224613f);
        p = fmaf(p, w, 0.00943887047f);
        p = fmaf(p, w, 1.00167406f);
        p = fmaf(p, w, 2.83297682f);
    }
    return p * x;
}

__device__ __forceinline__ float b2n(u32 b) {
    float f = __uint_as_float((b >> 9) | 0x3f800000u) - 1.0f;       // [0,1)
    float u = fmaxf(-0.99999994f, fmaf(f, 2.0f, -0.99999994f));
    return 1.41421356237309515f * erfinv_f(u);
}

__device__ __forceinline__ float splus(float v) {                    // logaddexp(v,0)
    return fmaxf(v, 0.0f) + log1pf(__expf(-fabsf(v)));
}
__device__ __forceinline__ float sigm(float v) {
    return __fdividef(1.0f, 1.0f + __expf(-v));
}
__device__ __forceinline__ float tanhx(float v) {
    float e = __expf(-2.0f * fabsf(v));
    float t = __fdividef(1.0f - e, 1.0f + e);
    return copysignf(t, v);
}

// ---------- prologue kernels ----------
__global__ void k_prep(const float* __restrict__ gk, const float* __restrict__ grk) {
    int i = blockIdx.x * 256 + threadIdx.x;
    if (i >= KPAD * 128) return;
    int k = i >> 7, c = i & 127;
    float wz = 0.0f, wr = 0.0f, wh = 0.0f;
    if (k < UNITS) {
        wz = grk[k * G3 + c];
        wr = grk[k * G3 + 128 + c];
        wh = grk[k * G3 + 256 + c];
    } else if (k < KTOT) {
        int f = k - UNITS;
        wz = gk[f * G3 + c];
        wr = gk[f * G3 + 128 + c];
        wh = gk[f * G3 + 256 + c];
    }
    int pr = k >> 1, hf = k & 1;
    g_Wp4[(pr * 128 + c) * 4 + hf * 2 + 0] = wz;
    g_Wp4[(pr * 128 + c) * 4 + hf * 2 + 1] = wr;
    g_Wp2[(pr * 128 + c) * 2 + hf] = wh;
}

__global__ void k_wdec(const float* __restrict__ loc, const float* __restrict__ rho) {
    int j = blockIdx.x * 256 + threadIdx.x;
    if (j >= GAMMA * NW) return;
    uint2 kk = tf2x32(0u, 42u, 0u, 0u);             // fold_in(key(42), 0)
    uint2 o  = tf2x32(kk.x, kk.y, 0u, (u32)j);      // partitionable draw
    float n  = b2n(o.x ^ o.y);
    int jj = j % NW;
    float sc = 1e-5f + 0.02f * splus(CC + rho[jj]);
    g_wdec[j] = loc[jj] + sc * n;
}

__global__ void k_eps() {
    int j = blockIdx.x * 512 + threadIdx.x;
    if (j >= NDEC * BTOT * NF) return;
    uint2 kk = tf2x32(0u, 42u, 0u, 1u);             // fold_in(key(42), 1)
    uint2 o  = tf2x32(kk.x, kk.y, 0u, (u32)j);
    g_eps[j] = b2n(o.x ^ o.y);
}

// ---------- fused GRU step: k processed in pairs (2 LDG per 2k) ----------
__device__ __forceinline__ void gru_step(float* hs, int tx, int ty,
                                         float bz, float br, float bxh, float brh) {
    const int r0 = ty * 8;
    u64 az[4], ar[4], ahr[4], ahx[4];
#pragma unroll
    for (int j = 0; j < 4; j++) { az[j] = 0ull; ar[j] = 0ull; ahr[j] = 0ull; ahx[j] = 0ull; }

    const float4* __restrict__ Wp4 = reinterpret_cast<const float4*>(g_Wp4) + tx;
    const float2* __restrict__ Wp2 = reinterpret_cast<const float2*>(g_Wp2) + tx;
    const float* hb = hs + r0;

#define PAIR_BODY(P, WC, VC, AH)                                                   \
    {                                                                              \
        const ulonglong2* hv0 = reinterpret_cast<const ulonglong2*>(hb + (2*(P)) * RP);   \
        const ulonglong2* hv1 = reinterpret_cast<const ulonglong2*>(hb + (2*(P)+1) * RP); \
        ulonglong2 c0 = hv0[0], c1 = hv0[1];                                       \
        ulonglong2 d0 = hv1[0], d1 = hv1[1];                                       \
        u64 wz0 = pk2(WC.x, WC.x), wr0 = pk2(WC.y, WC.y);                          \
        u64 wz1 = pk2(WC.z, WC.z), wr1 = pk2(WC.w, WC.w);                          \
        u64 wh0 = pk2(VC.x, VC.x), wh1 = pk2(VC.y, VC.y);                          \
        fma2(az[0], c0.x, wz0); fma2(az[1], c0.y, wz0);                            \
        fma2(az[2], c1.x, wz0); fma2(az[3], c1.y, wz0);                            \
        fma2(ar[0], c0.x, wr0); fma2(ar[1], c0.y, wr0);                            \
        fma2(ar[2], c1.x, wr0); fma2(ar[3], c1.y, wr0);                            \
        fma2(AH[0], c0.x, wh0); fma2(AH[1], c0.y, wh0);                            \
        fma2(AH[2], c1.x, wh0); fma2(AH[3], c1.y, wh0);                            \
        fma2(az[0], d0.x, wz1); fma2(az[1], d0.y, wz1);                            \
        fma2(az[2], d1.x, wz1); fma2(az[3], d1.y, wz1);                            \
        fma2(ar[0], d0.x, wr1); fma2(ar[1], d0.y, wr1);                            \
        fma2(ar[2], d1.x, wr1); fma2(ar[3], d1.y, wr1);                            \
        fma2(AH[0], d0.x, wh1); fma2(AH[1], d0.y, wh1);                            \
        fma2(AH[2], d1.x, wh1); fma2(AH[3], d1.y, wh1);                            \
    }

    // ---- phase 1: pairs 0..63 (k = 0..127, hidden state) -> ahr ----
    {
        float4 w0 = __ldg(&Wp4[0]);
        float4 w1 = __ldg(&Wp4[128]);
        float2 v0 = __ldg(&Wp2[0]);
        float2 v1 = __ldg(&Wp2[128]);
#pragma unroll 2
        for (int p = 0; p < 64; p++) {
            float4 wc = w0; float2 vc = v0;
            w0 = w1; v0 = v1;
            w1 = __ldg(&Wp4[(p + 2) * 128]);          // p+2 <= 65 < 90
            v1 = __ldg(&Wp2[(p + 2) * 128]);
            PAIR_BODY(p, wc, vc, ahr)
        }
    }
    // ---- phase 2: pairs 64..89 (k = 128..179, input; k=179 zero pad) -> ahx ----
    {
        float4 w0 = __ldg(&Wp4[64 * 128]);
        float4 w1 = __ldg(&Wp4[65 * 128]);
        float2 v0 = __ldg(&Wp2[64 * 128]);
        float2 v1 = __ldg(&Wp2[65 * 128]);
#pragma unroll 2
        for (int p = 64; p < NP; p++) {
            float4 wc = w0; float2 vc = v0;
            w0 = w1; v0 = v1;
            int pn = p + 2 < NP ? p + 2 : NP - 1;
            w1 = __ldg(&Wp4[pn * 128]);
            v1 = __ldg(&Wp2[pn * 128]);
            PAIR_BODY(p, wc, vc, ahx)
        }
    }
#undef PAIR_BODY

    // ---- epilogue ----
    float zv[8], hhv[8];
#pragma unroll
    for (int j = 0; j < 4; j++) {
        float2 vz = upk2(az[j]), vr = upk2(ar[j]);
        float2 vhr = upk2(ahr[j]), vhx = upk2(ahx[j]);
        float z0 = sigm(vz.x + bz), z1 = sigm(vz.y + bz);
        float q0 = sigm(vr.x + br), q1 = sigm(vr.y + br);
        zv[2 * j]     = z0;
        zv[2 * j + 1] = z1;
        hhv[2 * j]     = tanhx(vhx.x + bxh + q0 * (vhr.x + brh));
        hhv[2 * j + 1] = tanhx(vhx.y + bxh + q1 * (vhr.y + brh));
    }
    __syncthreads();            // all reads of hs complete
    float* hc = hs + tx * RP + r0;
#pragma unroll
    for (int j = 0; j < 8; j++) {
        float ho = hc[j];       // own column: only this thread touches it
        hc[j] = zv[j] * ho + (1.0f - zv[j]) * hhv[j];
    }
    __syncthreads();
}

// ---------- readout: t = h @ Kg + bg ----------
__device__ __forceinline__ void readout(const float* hs, float* ts, int g, int tx, int ty) {
    if (tx >= OUTD) return;
    const int r0 = ty * 8;
    u64 acc[4];
#pragma unroll
    for (int j = 0; j < 4; j++) acc[j] = 0ull;
    const float* __restrict__ wk = g_wdec + g * NW;
    float w0 = __ldg(&wk[tx]);
    float w1 = __ldg(&wk[OUTD + tx]);
#pragma unroll 4
    for (int k = 0; k < UNITS; k++) {
        float w = w0;
        w0 = w1;
        int kn = k + 2 < UNITS ? k + 2 : UNITS - 1;
        w1 = __ldg(&wk[kn * OUTD + tx]);
        u64 w2 = pk2(w, w);
        const ulonglong2* hv = reinterpret_cast<const ulonglong2*>(hs + k * RP + r0);
        ulonglong2 h0 = hv[0], h1 = hv[1];
        fma2(acc[0], h0.x, w2); fma2(acc[1], h0.y, w2);
        fma2(acc[2], h1.x, w2); fma2(acc[3], h1.y, w2);
    }
    float bias = __ldg(&wk[KW + tx]);
    float* tc = ts + tx * TSP + r0;
#pragma unroll
    for (int j = 0; j < 4; j++) {
        float2 v = upk2(acc[j]);
        tc[2 * j]     = v.x + bias;
        tc[2 * j + 1] = v.y + bias;
    }
}

// ---------- main persistent kernel ----------
__global__ void __launch_bounds__(NTH, 1)
irnn_main(const float* __restrict__ x, const float* __restrict__ gb,
          float* __restrict__ out) {
    extern __shared__ float sm[];
    float* hs = sm;                    // [KPAD][RP], row 179 = zero pad
    float* ts = sm + HS_F;             // [OUTD][TSP]
    const int tid = threadIdx.x;
    const int tx = tid & 127, ty = tid >> 7;
    const int b0 = (BTOT * blockIdx.x) / GRID;
    const int b1 = (BTOT * (blockIdx.x + 1)) / GRID;
    const int nr = b1 - b0;            // 55 or 56

    const float bz  = gb[tx] + gb[G3 + tx];
    const float br  = gb[128 + tx] + gb[G3 + 128 + tx];
    const float bxh = gb[256 + tx];
    const float brh = gb[G3 + 256 + tx];

    for (int i = tid; i < HS_F; i += NTH) hs[i] = 0.0f;   // h=0, x region, pad row
    __syncthreads();

    // ---- encoder: 50 steps ----
    for (int t = 0; t < TENC; t++) {
        for (int i = tid; i < ROWS * NF; i += NTH) {
            int rr = i / NF, f = i - rr * NF;
            float v = 0.0f;
            if (rr < nr)
                v = __ldg(&x[(size_t)(b0 + rr) * (TSEQ * NF) + t * NF + f]);
            hs[(UNITS + f) * RP + rr] = v;
        }
        __syncthreads();
        gru_step(hs, tx, ty, bz, br, bxh, brh);
    }

    // ---- readouts + decoder ----
    for (int g = 0; g < GAMMA; g++) {
        readout(hs, ts, g, tx, ty);
        __syncthreads();
        for (int i = tid; i < ROWS * OUTD; i += NTH) {
            int rr = i / OUTD, j = i - rr * OUTD;
            if (rr >= nr) continue;
            float v = ts[j * TSP + rr];
            if (j >= NF) v = 1e-5f + 0.05f * splus(CC + v);
            out[(size_t)(b0 + rr) * (GAMMA * OUTD) + g * OUTD + j] = v;
        }
        if (g == GAMMA - 1) break;
        __syncthreads();
        for (int i = tid; i < ROWS * NF; i += NTH) {
            int rr = i / NF, f = i - rr * NF;
            float loc = ts[f * TSP + rr];
            float sc = 1e-5f + 0.05f * splus(CC + ts[(NF + f) * TSP + rr]);
            float e = 0.0f;
            if (rr < nr)
                e = g_eps[((size_t)g * BTOT + b0 + rr) * NF + f];
            hs[(UNITS + f) * RP + rr] = loc + sc * e;
        }
        __syncthreads();
        gru_step(hs, tx, ty, bz, br, bxh, brh);
    }
}

// ---------- launcher ----------
extern "C" void kernel_launch(void* const* d_in, const int* in_sizes, int n_in,
                              void* d_out, int out_size) {
    const float* x   = (const float*)d_in[0];
    const float* gk  = (const float*)d_in[1];
    const float* grk = (const float*)d_in[2];
    const float* gb  = (const float*)d_in[3];
    const float* pl  = (const float*)d_in[4];
    const float* pr  = (const float*)d_in[5];
    float* out = (float*)d_out;

    cudaFuncSetAttribute(irnn_main, cudaFuncAttributeMaxDynamicSharedMemorySize,
                         SMFLOATS * (int)sizeof(float));

    k_prep<<<(KPAD * 128 + 255) / 256, 256>>>(gk, grk);
    k_wdec<<<(GAMMA * NW + 255) / 256, 256>>>(pl, pr);
    k_eps<<<(NDEC * BTOT * NF + 511) / 512, 512>>>();
    irnn_main<<<GRID, NTH, SMFLOATS * sizeof(float)>>>(x, gb, out);
}

// round 11
// speedup vs baseline: 1.0052x; 1.0052x over previous
#include <cuda_runtime.h>
#include <cstdint>

#define NF     51
#define UNITS  128
#define G3     384
#define TENC   50
#define NDEC   27
#define GAMMA  28
#define OUTD   102
#define KW     13056          // UNITS*OUTD
#define NW     13158
#define BTOT   8192
#define TSEQ   64
#define GRID   148
#define NTH    896            // 128 cols x 7 row-groups
#define ROWS   56             // max rows per CTA (8 per thread x 7 groups)
#define RP     60             // padded row stride (floats), 16B-aligned
#define KTOT   179            // 128 h + 51 input
#define KPAD   180            // 90 pairs
#define NP     90
#define TSP    58             // ts stride
#define CC     0.5413248546129181f

#define HS_F   (KPAD * RP)            // includes zero pad row k=179
#define TS_F   (OUTD * TSP)
#define SMFLOATS (HS_F + TS_F)

__device__ __align__(16) float g_Wp4[NP * 128 * 4];  // (wz0,wr0,wz1,wr1) per [pair][col]
__device__ __align__(16) float g_Wp2[NP * 128 * 2];  // (wh0,wh1)         per [pair][col]
__device__ __align__(16) float g_wdec[GAMMA * NW];
__device__ __align__(16) float g_eps[NDEC * BTOT * NF];

typedef unsigned long long u64;
typedef unsigned int u32;

// ---------- f32x2 helpers ----------
__device__ __forceinline__ u64 pk2(float lo, float hi) {
    u64 r; asm("mov.b64 %0, {%1, %2};" : "=l"(r) : "f"(lo), "f"(hi)); return r;
}
__device__ __forceinline__ float2 upk2(u64 v) {
    float2 f; asm("mov.b64 {%0, %1}, %2;" : "=f"(f.x), "=f"(f.y) : "l"(v)); return f;
}
__device__ __forceinline__ void fma2(u64& d, u64 a, u64 b) {
    asm("fma.rn.f32x2 %0, %1, %2, %0;" : "+l"(d) : "l"(a), "l"(b));
}

// ---------- JAX threefry2x32 (exact) ----------
__device__ __forceinline__ uint2 tf2x32(u32 k0, u32 k1, u32 x0, u32 x1) {
    u32 k2 = k0 ^ k1 ^ 0x1BD11BDAu;
#define TFR(r) { x0 += x1; x1 = (x1 << (r)) | (x1 >> (32 - (r))); x1 ^= x0; }
    x0 += k0; x1 += k1;
    TFR(13) TFR(15) TFR(26) TFR(6)   x0 += k1; x1 += k2 + 1u;
    TFR(17) TFR(29) TFR(16) TFR(24)  x0 += k2; x1 += k0 + 2u;
    TFR(13) TFR(15) TFR(26) TFR(6)   x0 += k0; x1 += k1 + 3u;
    TFR(17) TFR(29) TFR(16) TFR(24)  x0 += k1; x1 += k2 + 4u;
    TFR(13) TFR(15) TFR(26) TFR(6)   x0 += k2; x1 += k0 + 5u;
#undef TFR
    return make_uint2(x0, x1);
}

// XLA ErfInv f32 (Giles polynomial)
__device__ __forceinline__ float erfinv_f(float x) {
    float w = -log1pf(-x * x);
    float p;
    if (w < 5.0f) {
        w -= 2.5f;
        p = 2.81022636e-08f;
        p = fmaf(p, w, 3.43273939e-07f);
        p = fmaf(p, w, -3.5233877e-06f);
        p = fmaf(p, w, -4.39150654e-06f);
        p = fmaf(p, w, 0.00021858087f);
        p = fmaf(p, w, -0.00125372503f);
        p = fmaf(p, w, -0.00417768164f);
        p = fmaf(p, w, 0.246640727f);
        p = fmaf(p, w, 1.50140941f);
    } else {
        w = sqrtf(w) - 3.0f;
        p = -0.000200214257f;
        p = fmaf(p, w, 0.000100950558f);
        p = fmaf(p, w, 0.00134934322f);
        p = fmaf(p, w, -0.00367342844f);
        p = fmaf(p, w, 0.00573950773f);
        p = fmaf(p, w, -0.0076224613f);
        p = fmaf(p, w, 0.00943887047f);
        p = fmaf(p, w, 1.00167406f);
        p = fmaf(p, w, 2.83297682f);
    }
    return p * x;
}

__device__ __forceinline__ float b2n(u32 b) {
    float f = __uint_as_float((b >> 9) | 0x3f800000u) - 1.0f;       // [0,1)
    float u = fmaxf(-0.99999994f, fmaf(f, 2.0f, -0.99999994f));
    return 1.41421356237309515f * erfinv_f(u);
}

__device__ __forceinline__ float splus(float v) {                    // logaddexp(v,0)
    return fmaxf(v, 0.0f) + log1pf(__expf(-fabsf(v)));
}
__device__ __forceinline__ float sigm(float v) {
    return __fdividef(1.0f, 1.0f + __expf(-v));
}
__device__ __forceinline__ float tanhx(float v) {
    float e = __expf(-2.0f * fabsf(v));
    float t = __fdividef(1.0f - e, 1.0f + e);
    return copysignf(t, v);
}

// ---------- prologue kernels ----------
__global__ void k_prep(const float* __restrict__ gk, const float* __restrict__ grk) {
    int i = blockIdx.x * 256 + threadIdx.x;
    if (i >= KPAD * 128) return;
    int k = i >> 7, c = i & 127;
    float wz = 0.0f, wr = 0.0f, wh = 0.0f;
    if (k < UNITS) {
        wz = grk[k * G3 + c];
        wr = grk[k * G3 + 128 + c];
        wh = grk[k * G3 + 256 + c];
    } else if (k < KTOT) {
        int f = k - UNITS;
        wz = gk[f * G3 + c];
        wr = gk[f * G3 + 128 + c];
        wh = gk[f * G3 + 256 + c];
    }
    int pr = k >> 1, hf = k & 1;
    g_Wp4[(pr * 128 + c) * 4 + hf * 2 + 0] = wz;
    g_Wp4[(pr * 128 + c) * 4 + hf * 2 + 1] = wr;
    g_Wp2[(pr * 128 + c) * 2 + hf] = wh;
}

__global__ void k_wdec(const float* __restrict__ loc, const float* __restrict__ rho) {
    int j = blockIdx.x * 256 + threadIdx.x;
    if (j >= GAMMA * NW) return;
    uint2 kk = tf2x32(0u, 42u, 0u, 0u);             // fold_in(key(42), 0)
    uint2 o  = tf2x32(kk.x, kk.y, 0u, (u32)j);      // partitionable draw
    float n  = b2n(o.x ^ o.y);
    int jj = j % NW;
    float sc = 1e-5f + 0.02f * splus(CC + rho[jj]);
    g_wdec[j] = loc[jj] + sc * n;
}

__global__ void k_eps() {
    int j = blockIdx.x * 512 + threadIdx.x;
    if (j >= NDEC * BTOT * NF) return;
    uint2 kk = tf2x32(0u, 42u, 0u, 1u);             // fold_in(key(42), 1)
    uint2 o  = tf2x32(kk.x, kk.y, 0u, (u32)j);
    g_eps[j] = b2n(o.x ^ o.y);
}

// ---------- fused GRU step: k processed in pairs (2 LDG per 2k) ----------
__device__ __forceinline__ void gru_step(float* hs, int tx, int ty,
                                         float bz, float br, float bxh, float brh) {
    const int r0 = ty * 8;
    u64 az[4], ar[4], ahr[4], ahx[4];
#pragma unroll
    for (int j = 0; j < 4; j++) { az[j] = 0ull; ar[j] = 0ull; ahr[j] = 0ull; ahx[j] = 0ull; }

    const float4* __restrict__ Wp4 = reinterpret_cast<const float4*>(g_Wp4) + tx;
    const float2* __restrict__ Wp2 = reinterpret_cast<const float2*>(g_Wp2) + tx;
    const float* hb = hs + r0;

#define PAIR_BODY(P, WC, VC, AH)                                                   \
    {                                                                              \
        const ulonglong2* hv0 = reinterpret_cast<const ulonglong2*>(hb + (2*(P)) * RP);   \
        const ulonglong2* hv1 = reinterpret_cast<const ulonglong2*>(hb + (2*(P)+1) * RP); \
        ulonglong2 c0 = hv0[0], c1 = hv0[1];                                       \
        ulonglong2 d0 = hv1[0], d1 = hv1[1];                                       \
        u64 wz0 = pk2(WC.x, WC.x), wr0 = pk2(WC.y, WC.y);                          \
        u64 wz1 = pk2(WC.z, WC.z), wr1 = pk2(WC.w, WC.w);                          \
        u64 wh0 = pk2(VC.x, VC.x), wh1 = pk2(VC.y, VC.y);                          \
        fma2(az[0], c0.x, wz0); fma2(az[1], c0.y, wz0);                            \
        fma2(az[2], c1.x, wz0); fma2(az[3], c1.y, wz0);                            \
        fma2(ar[0], c0.x, wr0); fma2(ar[1], c0.y, wr0);                            \
        fma2(ar[2], c1.x, wr0); fma2(ar[3], c1.y, wr0);                            \
        fma2(AH[0], c0.x, wh0); fma2(AH[1], c0.y, wh0);                            \
        fma2(AH[2], c1.x, wh0); fma2(AH[3], c1.y, wh0);                            \
        fma2(az[0], d0.x, wz1); fma2(az[1], d0.y, wz1);                            \
        fma2(az[2], d1.x, wz1); fma2(az[3], d1.y, wz1);                            \
        fma2(ar[0], d0.x, wr1); fma2(ar[1], d0.y, wr1);                            \
        fma2(ar[2], d1.x, wr1); fma2(ar[3], d1.y, wr1);                            \
        fma2(AH[0], d0.x, wh1); fma2(AH[1], d0.y, wh1);                            \
        fma2(AH[2], d1.x, wh1); fma2(AH[3], d1.y, wh1);                            \
    }

    // ---- phase 1: pairs 0..63 (k = 0..127, hidden state) -> ahr ----
    {
        float4 w0 = __ldg(&Wp4[0]);
        float4 w1 = __ldg(&Wp4[128]);
        float2 v0 = __ldg(&Wp2[0]);
        float2 v1 = __ldg(&Wp2[128]);
#pragma unroll 2
        for (int p = 0; p < 64; p++) {
            float4 wc = w0; float2 vc = v0;
            w0 = w1; v0 = v1;
            w1 = __ldg(&Wp4[(p + 2) * 128]);          // p+2 <= 65 < 90
            v1 = __ldg(&Wp2[(p + 2) * 128]);
            PAIR_BODY(p, wc, vc, ahr)
        }
    }
    // ---- phase 2: pairs 64..89 (k = 128..179, input; k=179 zero pad) -> ahx ----
    {
        float4 w0 = __ldg(&Wp4[64 * 128]);
        float4 w1 = __ldg(&Wp4[65 * 128]);
        float2 v0 = __ldg(&Wp2[64 * 128]);
        float2 v1 = __ldg(&Wp2[65 * 128]);
#pragma unroll 2
        for (int p = 64; p < NP; p++) {
            float4 wc = w0; float2 vc = v0;
            w0 = w1; v0 = v1;
            int pn = p + 2 < NP ? p + 2 : NP - 1;
            w1 = __ldg(&Wp4[pn * 128]);
            v1 = __ldg(&Wp2[pn * 128]);
            PAIR_BODY(p, wc, vc, ahx)
        }
    }
#undef PAIR_BODY

    // ---- epilogue ----
    float zv[8], hhv[8];
#pragma unroll
    for (int j = 0; j < 4; j++) {
        float2 vz = upk2(az[j]), vr = upk2(ar[j]);
        float2 vhr = upk2(ahr[j]), vhx = upk2(ahx[j]);
        float z0 = sigm(vz.x + bz), z1 = sigm(vz.y + bz);
        float q0 = sigm(vr.x + br), q1 = sigm(vr.y + br);
        zv[2 * j]     = z0;
        zv[2 * j + 1] = z1;
        hhv[2 * j]     = tanhx(vhx.x + bxh + q0 * (vhr.x + brh));
        hhv[2 * j + 1] = tanhx(vhx.y + bxh + q1 * (vhr.y + brh));
    }
    __syncthreads();            // all reads of hs complete
    float* hc = hs + tx * RP + r0;
#pragma unroll
    for (int j = 0; j < 8; j++) {
        float ho = hc[j];       // own column: only this thread touches it
        hc[j] = zv[j] * ho + (1.0f - zv[j]) * hhv[j];
    }
    __syncthreads();
}

// ---------- readout: t = h @ Kg + bg ----------
__device__ __forceinline__ void readout(const float* hs, float* ts, int g, int tx, int ty) {
    if (tx >= OUTD) return;
    const int r0 = ty * 8;
    u64 acc[4];
#pragma unroll
    for (int j = 0; j < 4; j++) acc[j] = 0ull;
    const float* __restrict__ wk = g_wdec + g * NW;
    float w0 = __ldg(&wk[tx]);
    float w1 = __ldg(&wk[OUTD + tx]);
#pragma unroll 4
    for (int k = 0; k < UNITS; k++) {
        float w = w0;
        w0 = w1;
        int kn = k + 2 < UNITS ? k + 2 : UNITS - 1;
        w1 = __ldg(&wk[kn * OUTD + tx]);
        u64 w2 = pk2(w, w);
        const ulonglong2* hv = reinterpret_cast<const ulonglong2*>(hs + k * RP + r0);
        ulonglong2 h0 = hv[0], h1 = hv[1];
        fma2(acc[0], h0.x, w2); fma2(acc[1], h0.y, w2);
        fma2(acc[2], h1.x, w2); fma2(acc[3], h1.y, w2);
    }
    float bias = __ldg(&wk[KW + tx]);
    float* tc = ts + tx * TSP + r0;
#pragma unroll
    for (int j = 0; j < 4; j++) {
        float2 v = upk2(acc[j]);
        tc[2 * j]     = v.x + bias;
        tc[2 * j + 1] = v.y + bias;
    }
}

// ---------- main persistent kernel ----------
__global__ void __launch_bounds__(NTH, 1)
irnn_main(const float* __restrict__ x, const float* __restrict__ gb,
          float* __restrict__ out) {
    extern __shared__ float sm[];
    float* hs = sm;                    // [KPAD][RP], row 179 = zero pad
    float* ts = sm + HS_F;             // [OUTD][TSP]
    const int tid = threadIdx.x;
    const int tx = tid & 127, ty = tid >> 7;
    const int b0 = (BTOT * blockIdx.x) / GRID;
    const int b1 = (BTOT * (blockIdx.x + 1)) / GRID;
    const int nr = b1 - b0;            // 55 or 56

    const float bz  = gb[tx] + gb[G3 + tx];
    const float br  = gb[128 + tx] + gb[G3 + 128 + tx];
    const float bxh = gb[256 + tx];
    const float brh = gb[G3 + 256 + tx];

    for (int i = tid; i < HS_F; i += NTH) hs[i] = 0.0f;   // h=0, x region, pad row
    __syncthreads();

    // ---- encoder: 50 steps ----
    for (int t = 0; t < TENC; t++) {
        for (int i = tid; i < ROWS * NF; i += NTH) {
            int rr = i / NF, f = i - rr * NF;
            float v = 0.0f;
            if (rr < nr)
                v = __ldg(&x[(size_t)(b0 + rr) * (TSEQ * NF) + t * NF + f]);
            hs[(UNITS + f) * RP + rr] = v;
        }
        __syncthreads();
        gru_step(hs, tx, ty, bz, br, bxh, brh);
    }

    // ---- readouts + decoder ----
    for (int g = 0; g < GAMMA; g++) {
        readout(hs, ts, g, tx, ty);
        __syncthreads();
        for (int i = tid; i < ROWS * OUTD; i += NTH) {
            int rr = i / OUTD, j = i - rr * OUTD;
            if (rr >= nr) continue;
            float v = ts[j * TSP + rr];
            if (j >= NF) v = 1e-5f + 0.05f * splus(CC + v);
            out[(size_t)(b0 + rr) * (GAMMA * OUTD) + g * OUTD + j] = v;
        }
        if (g == GAMMA - 1) break;
        __syncthreads();
        for (int i = tid; i < ROWS * NF; i += NTH) {
            int rr = i / NF, f = i - rr * NF;
            float loc = ts[f * TSP + rr];
            float sc = 1e-5f + 0.05f * splus(CC + ts[(NF + f) * TSP + rr]);
            float e = 0.0f;
            if (rr < nr)
                e = g_eps[((size_t)g * BTOT + b0 + rr) * NF + f];
            hs[(UNITS + f) * RP + rr] = loc + sc * e;
        }
        __syncthreads();
        gru_step(hs, tx, ty, bz, br, bxh, brh);
    }
}

// ---------- launcher ----------
extern "C" void kernel_launch(void* const* d_in, const int* in_sizes, int n_in,
                              void* d_out, int out_size) {
    const float* x   = (const float*)d_in[0];
    const float* gk  = (const float*)d_in[1];
    const float* grk = (const float*)d_in[2];
    const float* gb  = (const float*)d_in[3];
    const float* pl  = (const float*)d_in[4];
    const float* pr  = (const float*)d_in[5];
    float* out = (float*)d_out;

    cudaFuncSetAttribute(irnn_main, cudaFuncAttributeMaxDynamicSharedMemorySize,
                         SMFLOATS * (int)sizeof(float));

    k_prep<<<(KPAD * 128 + 255) / 256, 256>>>(gk, grk);
    k_wdec<<<(GAMMA * NW + 255) / 256, 256>>>(pl, pr);
    k_eps<<<(NDEC * BTOT * NF + 511) / 512, 512>>>();
    irnn_main<<<GRID, NTH, SMFLOATS * sizeof(float)>>>(x, gb, out);
}

// round 12
// speedup vs baseline: 1.0539x; 1.0485x over previous
#include <cuda_runtime.h>
#include <cstdint>

#define NF     51
#define UNITS  128
#define G3     384
#define TENC   50
#define NDEC   27
#define GAMMA  28
#define OUTD   102
#define KW     13056          // UNITS*OUTD
#define NW     13158
#define BTOT   8192
#define TSEQ   64
#define GRID   148
#define NTH    896            // 128 cols x 7 row-groups
#define ROWS   56             // max rows per CTA (8 per thread x 7 groups)
#define RP     60             // padded row stride (floats), 16B-aligned
#define KTOT   179            // 128 h + 51 input
#define KPAD   180            // +1 zero pad row
#define NX     52             // x-part rows incl pad (128..179)
#define TSP    58             // ts stride
#define CC     0.5413248546129181f

#define HS_F   (KPAD * RP)            // 10800
#define TS_F   (OUTD * TSP)           // 5916
#define WH_F   (KPAD * 128)           // 23040 : wh for all k (SMEM-resident)
#define WX_F   (NX * 128 * 2)         // 13312 : (wz,wr) for x-part (SMEM-resident)
#define SMFLOATS (HS_F + TS_F + WH_F + WX_F)   // 53068 floats = 212 KB

__device__ __align__(16) float2 g_Wzr[KPAD * 128];    // (wz,wr) per [k][col], row 179 zero
__device__ __align__(16) float  g_Wh [KPAD * 128];    // wh      per [k][col], row 179 zero
__device__ __align__(16) float  g_wdec[GAMMA * NW];
__device__ __align__(16) float  g_eps[NDEC * BTOT * NF];

typedef unsigned long long u64;
typedef unsigned int u32;

// ---------- f32x2 helpers ----------
__device__ __forceinline__ u64 pk2(float lo, float hi) {
    u64 r; asm("mov.b64 %0, {%1, %2};" : "=l"(r) : "f"(lo), "f"(hi)); return r;
}
__device__ __forceinline__ float2 upk2(u64 v) {
    float2 f; asm("mov.b64 {%0, %1}, %2;" : "=f"(f.x), "=f"(f.y) : "l"(v)); return f;
}
__device__ __forceinline__ void fma2(u64& d, u64 a, u64 b) {
    asm("fma.rn.f32x2 %0, %1, %2, %0;" : "+l"(d) : "l"(a), "l"(b));
}

// ---------- JAX threefry2x32 (exact) ----------
__device__ __forceinline__ uint2 tf2x32(u32 k0, u32 k1, u32 x0, u32 x1) {
    u32 k2 = k0 ^ k1 ^ 0x1BD11BDAu;
#define TFR(r) { x0 += x1; x1 = (x1 << (r)) | (x1 >> (32 - (r))); x1 ^= x0; }
    x0 += k0; x1 += k1;
    TFR(13) TFR(15) TFR(26) TFR(6)   x0 += k1; x1 += k2 + 1u;
    TFR(17) TFR(29) TFR(16) TFR(24)  x0 += k2; x1 += k0 + 2u;
    TFR(13) TFR(15) TFR(26) TFR(6)   x0 += k0; x1 += k1 + 3u;
    TFR(17) TFR(29) TFR(16) TFR(24)  x0 += k1; x1 += k2 + 4u;
    TFR(13) TFR(15) TFR(26) TFR(6)   x0 += k2; x1 += k0 + 5u;
#undef TFR
    return make_uint2(x0, x1);
}

// XLA ErfInv f32 (Giles polynomial)
__device__ __forceinline__ float erfinv_f(float x) {
    float w = -log1pf(-x * x);
    float p;
    if (w < 5.0f) {
        w -= 2.5f;
        p = 2.81022636e-08f;
        p = fmaf(p, w, 3.43273939e-07f);
        p = fmaf(p, w, -3.5233877e-06f);
        p = fmaf(p, w, -4.39150654e-06f);
        p = fmaf(p, w, 0.00021858087f);
        p = fmaf(p, w, -0.00125372503f);
        p = fmaf(p, w, -0.00417768164f);
        p = fmaf(p, w, 0.246640727f);
        p = fmaf(p, w, 1.50140941f);
    } else {
        w = sqrtf(w) - 3.0f;
        p = -0.000200214257f;
        p = fmaf(p, w, 0.000100950558f);
        p = fmaf(p, w, 0.00134934322f);
        p = fmaf(p, w, -0.00367342844f);
        p = fmaf(p, w, 0.00573950773f);
        p = fmaf(p, w, -0.0076224613f);
        p = fmaf(p, w, 0.00943887047f);
        p = fmaf(p, w, 1.00167406f);
        p = fmaf(p, w, 2.83297682f);
    }
    return p * x;
}

__device__ __forceinline__ float b2n(u32 b) {
    float f = __uint_as_float((b >> 9) | 0x3f800000u) - 1.0f;       // [0,1)
    float u = fmaxf(-0.99999994f, fmaf(f, 2.0f, -0.99999994f));
    return 1.41421356237309515f * erfinv_f(u);
}

__device__ __forceinline__ float splus(float v) {                    // logaddexp(v,0)
    return fmaxf(v, 0.0f) + log1pf(__expf(-fabsf(v)));
}
__device__ __forceinline__ float sigm(float v) {
    return __fdividef(1.0f, 1.0f + __expf(-v));
}
__device__ __forceinline__ float tanhx(float v) {
    float e = __expf(-2.0f * fabsf(v));
    float t = __fdividef(1.0f - e, 1.0f + e);
    return copysignf(t, v);
}

// ---------- prologue kernels ----------
__global__ void k_prep(const float* __restrict__ gk, const float* __restrict__ grk) {
    int i = blockIdx.x * 256 + threadIdx.x;
    if (i >= KPAD * 128) return;
    int k = i >> 7, c = i & 127;
    float wz = 0.0f, wr = 0.0f, wh = 0.0f;
    if (k < UNITS) {
        wz = grk[k * G3 + c];
        wr = grk[k * G3 + 128 + c];
        wh = grk[k * G3 + 256 + c];
    } else if (k < KTOT) {
        int f = k - UNITS;
        wz = gk[f * G3 + c];
        wr = gk[f * G3 + 128 + c];
        wh = gk[f * G3 + 256 + c];
    }
    g_Wzr[i] = make_float2(wz, wr);
    g_Wh[i]  = wh;
}

__global__ void k_wdec(const float* __restrict__ loc, const float* __restrict__ rho) {
    int j = blockIdx.x * 256 + threadIdx.x;
    if (j >= GAMMA * NW) return;
    uint2 kk = tf2x32(0u, 42u, 0u, 0u);             // fold_in(key(42), 0)
    uint2 o  = tf2x32(kk.x, kk.y, 0u, (u32)j);      // partitionable draw
    float n  = b2n(o.x ^ o.y);
    int jj = j % NW;
    float sc = 1e-5f + 0.02f * splus(CC + rho[jj]);
    g_wdec[j] = loc[jj] + sc * n;
}

__global__ void k_eps() {
    int j = blockIdx.x * 512 + threadIdx.x;
    if (j >= NDEC * BTOT * NF) return;
    uint2 kk = tf2x32(0u, 42u, 0u, 1u);             // fold_in(key(42), 1)
    uint2 o  = tf2x32(kk.x, kk.y, 0u, (u32)j);
    g_eps[j] = b2n(o.x ^ o.y);
}

// ---------- fused GRU step ----------
// Phase 1 (k=0..127): wzr via LDG stream (dist-2 prefetch), wh via SMEM.
// Phase 2 (k=128..178): all weights SMEM-resident -> zero LDG.
__device__ __forceinline__ void gru_step(float* hs, const float* swh, const float* swx,
                                         int tx, int ty,
                                         float bz, float br, float bxh, float brh) {
    const int r0 = ty * 8;
    u64 az[4], ar[4], ahr[4], ahx[4];
#pragma unroll
    for (int j = 0; j < 4; j++) { az[j] = 0ull; ar[j] = 0ull; ahr[j] = 0ull; ahx[j] = 0ull; }

    const float2* __restrict__ Wzr = g_Wzr + tx;
    const float* hb = hs + r0;
    const float* whp = swh + tx;

    // ---- phase 1: k = 0..127 (hidden state) -> ahr ----
    {
        float2 w0 = __ldg(&Wzr[0]);
        float2 w1 = __ldg(&Wzr[128]);
#pragma unroll 4
        for (int k = 0; k < UNITS; k++) {
            float2 wc = w0;
            w0 = w1;
            w1 = __ldg(&Wzr[(k + 2) * 128]);          // k+2 <= 129 < KTOT
            float vc = whp[k * 128];                   // SMEM, broadcast
            const ulonglong2* hv = reinterpret_cast<const ulonglong2*>(hb + k * RP);
            ulonglong2 h0 = hv[0], h1 = hv[1];
            u64 wz = pk2(wc.x, wc.x), wr = pk2(wc.y, wc.y), wh = pk2(vc, vc);
            fma2(az[0], h0.x, wz); fma2(az[1], h0.y, wz);
            fma2(az[2], h1.x, wz); fma2(az[3], h1.y, wz);
            fma2(ar[0], h0.x, wr); fma2(ar[1], h0.y, wr);
            fma2(ar[2], h1.x, wr); fma2(ar[3], h1.y, wr);
            fma2(ahr[0], h0.x, wh); fma2(ahr[1], h0.y, wh);
            fma2(ahr[2], h1.x, wh); fma2(ahr[3], h1.y, wh);
        }
    }
    // ---- phase 2: k = 128..178 (input) -> ahx ; all weights in SMEM ----
    {
        const float2* __restrict__ wxp = reinterpret_cast<const float2*>(swx) + tx;
#pragma unroll 4
        for (int j = 0; j < KTOT - UNITS; j++) {
            float2 wc = wxp[j * 128];                  // SMEM
            float vc = whp[(UNITS + j) * 128];         // SMEM
            const ulonglong2* hv = reinterpret_cast<const ulonglong2*>(hb + (UNITS + j) * RP);
            ulonglong2 h0 = hv[0], h1 = hv[1];
            u64 wz = pk2(wc.x, wc.x), wr = pk2(wc.y, wc.y), wh = pk2(vc, vc);
            fma2(az[0], h0.x, wz); fma2(az[1], h0.y, wz);
            fma2(az[2], h1.x, wz); fma2(az[3], h1.y, wz);
            fma2(ar[0], h0.x, wr); fma2(ar[1], h0.y, wr);
            fma2(ar[2], h1.x, wr); fma2(ar[3], h1.y, wr);
            fma2(ahx[0], h0.x, wh); fma2(ahx[1], h0.y, wh);
            fma2(ahx[2], h1.x, wh); fma2(ahx[3], h1.y, wh);
        }
    }
    // ---- epilogue ----
    float zv[8], hhv[8];
#pragma unroll
    for (int j = 0; j < 4; j++) {
        float2 vz = upk2(az[j]), vr = upk2(ar[j]);
        float2 vhr = upk2(ahr[j]), vhx = upk2(ahx[j]);
        float z0 = sigm(vz.x + bz), z1 = sigm(vz.y + bz);
        float q0 = sigm(vr.x + br), q1 = sigm(vr.y + br);
        zv[2 * j]     = z0;
        zv[2 * j + 1] = z1;
        hhv[2 * j]     = tanhx(vhx.x + bxh + q0 * (vhr.x + brh));
        hhv[2 * j + 1] = tanhx(vhx.y + bxh + q1 * (vhr.y + brh));
    }
    __syncthreads();            // all reads of hs complete
    float* hc = hs + tx * RP + r0;
#pragma unroll
    for (int j = 0; j < 8; j++) {
        float ho = hc[j];       // own column: only this thread touches it
        hc[j] = zv[j] * ho + (1.0f - zv[j]) * hhv[j];
    }
    __syncthreads();
}

// ---------- readout: t = h @ Kg + bg ----------
__device__ __forceinline__ void readout(const float* hs, float* ts, int g, int tx, int ty) {
    if (tx >= OUTD) return;
    const int r0 = ty * 8;
    u64 acc[4];
#pragma unroll
    for (int j = 0; j < 4; j++) acc[j] = 0ull;
    const float* __restrict__ wk = g_wdec + g * NW;
    float w0 = __ldg(&wk[tx]);
    float w1 = __ldg(&wk[OUTD + tx]);
#pragma unroll 4
    for (int k = 0; k < UNITS; k++) {
        float w = w0;
        w0 = w1;
        int kn = k + 2 < UNITS ? k + 2 : UNITS - 1;
        w1 = __ldg(&wk[kn * OUTD + tx]);
        u64 w2 = pk2(w, w);
        const ulonglong2* hv = reinterpret_cast<const ulonglong2*>(hs + k * RP + r0);
        ulonglong2 h0 = hv[0], h1 = hv[1];
        fma2(acc[0], h0.x, w2); fma2(acc[1], h0.y, w2);
        fma2(acc[2], h1.x, w2); fma2(acc[3], h1.y, w2);
    }
    float bias = __ldg(&wk[KW + tx]);
    float* tc = ts + tx * TSP + r0;
#pragma unroll
    for (int j = 0; j < 4; j++) {
        float2 v = upk2(acc[j]);
        tc[2 * j]     = v.x + bias;
        tc[2 * j + 1] = v.y + bias;
    }
}

// ---------- main persistent kernel ----------
__global__ void __launch_bounds__(NTH, 1)
irnn_main(const float* __restrict__ x, const float* __restrict__ gb,
          float* __restrict__ out) {
    extern __shared__ float sm[];
    float* hs  = sm;                       // [KPAD][RP], row 179 zero pad
    float* ts  = sm + HS_F;                // [OUTD][TSP]
    float* swh = sm + HS_F + TS_F;         // [KPAD][128] wh
    float* swx = swh + WH_F;               // [NX][128] float2 (wz,wr) x-part
    const int tid = threadIdx.x;
    const int tx = tid & 127, ty = tid >> 7;
    const int b0 = (BTOT * blockIdx.x) / GRID;
    const int b1 = (BTOT * (blockIdx.x + 1)) / GRID;
    const int nr = b1 - b0;            // 55 or 56

    const float bz  = gb[tx] + gb[G3 + tx];
    const float br  = gb[128 + tx] + gb[G3 + 128 + tx];
    const float bxh = gb[256 + tx];
    const float brh = gb[G3 + 256 + tx];

    for (int i = tid; i < HS_F; i += NTH) hs[i] = 0.0f;   // h=0, x region, pad row
    // stage SMEM-resident weights (once per kernel)
    for (int i = tid; i < WH_F; i += NTH) swh[i] = g_Wh[i];
    {
        const float* wsrc = reinterpret_cast<const float*>(g_Wzr) + UNITS * 128 * 2;
        for (int i = tid; i < WX_F; i += NTH) swx[i] = wsrc[i];
    }
    __syncthreads();

    // ---- encoder: 50 steps ----
    for (int t = 0; t < TENC; t++) {
        for (int i = tid; i < ROWS * NF; i += NTH) {
            int rr = i / NF, f = i - rr * NF;
            float v = 0.0f;
            if (rr < nr)
                v = __ldg(&x[(size_t)(b0 + rr) * (TSEQ * NF) + t * NF + f]);
            hs[(UNITS + f) * RP + rr] = v;
        }
        __syncthreads();
        gru_step(hs, swh, swx, tx, ty, bz, br, bxh, brh);
    }

    // ---- readouts + decoder ----
    for (int g = 0; g < GAMMA; g++) {
        readout(hs, ts, g, tx, ty);
        __syncthreads();
        for (int i = tid; i < ROWS * OUTD; i += NTH) {
            int rr = i / OUTD, j = i - rr * OUTD;
            if (rr >= nr) continue;
            float v = ts[j * TSP + rr];
            if (j >= NF) v = 1e-5f + 0.05f * splus(CC + v);
            out[(size_t)(b0 + rr) * (GAMMA * OUTD) + g * OUTD + j] = v;
        }
        if (g == GAMMA - 1) break;
        __syncthreads();
        for (int i = tid; i < ROWS * NF; i += NTH) {
            int rr = i / NF, f = i - rr * NF;
            float loc = ts[f * TSP + rr];
            float sc = 1e-5f + 0.05f * splus(CC + ts[(NF + f) * TSP + rr]);
            float e = 0.0f;
            if (rr < nr)
                e = g_eps[((size_t)g * BTOT + b0 + rr) * NF + f];
            hs[(UNITS + f) * RP + rr] = loc + sc * e;
        }
        __syncthreads();
        gru_step(hs, swh, swx, tx, ty, bz, br, bxh, brh);
    }
}

// ---------- launcher ----------
extern "C" void kernel_launch(void* const* d_in, const int* in_sizes, int n_in,
                              void* d_out, int out_size) {
    const float* x   = (const float*)d_in[0];
    const float* gk  = (const float*)d_in[1];
    const float* grk = (const float*)d_in[2];
    const float* gb  = (const float*)d_in[3];
    const float* pl  = (const float*)d_in[4];
    const float* pr  = (const float*)d_in[5];
    float* out = (float*)d_out;

    cudaFuncSetAttribute(irnn_main, cudaFuncAttributeMaxDynamicSharedMemorySize,
                         SMFLOATS * (int)sizeof(float));

    k_prep<<<(KPAD * 128 + 255) / 256, 256>>>(gk, grk);
    k_wdec<<<(GAMMA * NW + 255) / 256, 256>>>(pl, pr);
    k_eps<<<(NDEC * BTOT * NF + 511) / 512, 512>>>();
    irnn_main<<<GRID, NTH, SMFLOATS * sizeof(float)>>>(x, gb, out);
}